// round 1
// baseline (speedup 1.0000x reference)
#include <cuda_runtime.h>
#include <cuda_bf16.h>
#include <math.h>

// ---------------- problem constants ----------------
#define BB   2
#define TT   1024
#define EE   1024
#define HH   16
#define DD   64
#define FFN  4096
#define VV   32000
#define LL   6
#define MM   (BB*TT)          // 2048 rows

// ---------------- scratch (device globals; no allocation allowed) ----------
__device__ float g_x[MM*EE];
__device__ float g_h[MM*EE];
__device__ float g_q[MM*EE];
__device__ float g_k[MM*EE];
__device__ float g_v[MM*EE];
__device__ float g_o[MM*EE];
__device__ float g_f[MM*FFN];

// ---------------- embedding: x = tok_emb[idx] + pos_emb[t] ----------------
__global__ void embed_kernel(const int* __restrict__ idx,
                             const float* __restrict__ tok,
                             const float* __restrict__ pos)
{
    int row = blockIdx.x;              // 0..2047
    int t   = row & (TT-1);
    int tokid = idx[row];
    const float4* t4 = (const float4*)(tok + (size_t)tokid * EE);
    const float4* p4 = (const float4*)(pos + (size_t)t * EE);
    float4* x4 = (float4*)(g_x + (size_t)row * EE);
    int j = threadIdx.x;               // 256 threads * 4 floats = 1024
    float4 a = t4[j], b = p4[j];
    a.x += b.x; a.y += b.y; a.z += b.z; a.w += b.w;
    x4[j] = a;
}

// ---------------- layernorm over E=1024, 256 threads/row ----------------
__global__ void ln_kernel(const float* __restrict__ x,
                          const float* __restrict__ g,
                          const float* __restrict__ b,
                          float* __restrict__ y)
{
    __shared__ float red[256];
    __shared__ float s_mu, s_inv;
    int row = blockIdx.x;
    int tid = threadIdx.x;
    const float4* xr = (const float4*)(x + (size_t)row * EE);
    float4 xv = xr[tid];

    float s = xv.x + xv.y + xv.z + xv.w;
    red[tid] = s; __syncthreads();
    for (int o = 128; o > 0; o >>= 1) { if (tid < o) red[tid] += red[tid+o]; __syncthreads(); }
    if (tid == 0) s_mu = red[0] * (1.0f/EE);
    __syncthreads();
    float mu = s_mu;

    float d0 = xv.x-mu, d1 = xv.y-mu, d2 = xv.z-mu, d3 = xv.w-mu;
    s = d0*d0 + d1*d1 + d2*d2 + d3*d3;
    __syncthreads();
    red[tid] = s; __syncthreads();
    for (int o = 128; o > 0; o >>= 1) { if (tid < o) red[tid] += red[tid+o]; __syncthreads(); }
    if (tid == 0) s_inv = rsqrtf(red[0] * (1.0f/EE) + 1e-5f);
    __syncthreads();
    float inv = s_inv;

    float4 gv = ((const float4*)g)[tid];
    float4 bv = ((const float4*)b)[tid];
    float4 out;
    out.x = d0*inv*gv.x + bv.x;
    out.y = d1*inv*gv.y + bv.y;
    out.z = d2*inv*gv.z + bv.z;
    out.w = d3*inv*gv.w + bv.w;
    ((float4*)(y + (size_t)row * EE))[tid] = out;
}

// ---------------- SGEMM 128x128x8, 256 threads, 8x8 micro-tile -------------
// C[M,N] = A[M,K] @ W[K,N] (+bias[N]) (+res[M,N]) (relu)
#define BM 128
#define BN 128
#define BK 8

__global__ __launch_bounds__(256, 2)
void sgemm_kernel(const float* __restrict__ A, const float* __restrict__ W,
                  const float* __restrict__ bias, const float* __restrict__ res,
                  float* __restrict__ C, int M, int N, int K, int do_relu)
{
    __shared__ float As[BK][BM];
    __shared__ float Bs[BK][BN];

    int tid = threadIdx.x;
    int row0 = blockIdx.y * BM;
    int col0 = blockIdx.x * BN;

    int arow = tid >> 1;            // 0..127
    int acol = (tid & 1) * 4;       // 0 or 4
    int brow = tid >> 5;            // 0..7
    int bcol = (tid & 31) * 4;      // 0..124

    int tx = tid & 15;              // 0..15
    int ty = tid >> 4;              // 0..15

    float acc[8][8];
    #pragma unroll
    for (int i = 0; i < 8; i++)
        #pragma unroll
        for (int j = 0; j < 8; j++) acc[i][j] = 0.f;

    const float* Aptr = A + (size_t)(row0 + arow) * K + acol;
    const float* Bptr = W + (size_t)brow * N + col0 + bcol;

    for (int k0 = 0; k0 < K; k0 += BK) {
        float4 a4 = *(const float4*)(Aptr + k0);
        As[acol+0][arow] = a4.x;
        As[acol+1][arow] = a4.y;
        As[acol+2][arow] = a4.z;
        As[acol+3][arow] = a4.w;
        float4 b4 = *(const float4*)(Bptr + (size_t)k0 * N);
        *(float4*)&Bs[brow][bcol] = b4;
        __syncthreads();

        #pragma unroll
        for (int k = 0; k < BK; k++) {
            float ra[8], rb[8];
            *(float4*)&ra[0] = *(const float4*)&As[k][ty*4];
            *(float4*)&ra[4] = *(const float4*)&As[k][64 + ty*4];
            *(float4*)&rb[0] = *(const float4*)&Bs[k][tx*4];
            *(float4*)&rb[4] = *(const float4*)&Bs[k][64 + tx*4];
            #pragma unroll
            for (int i = 0; i < 8; i++)
                #pragma unroll
                for (int j = 0; j < 8; j++)
                    acc[i][j] += ra[i] * rb[j];
        }
        __syncthreads();
    }

    // epilogue: split rows/cols into low-64 and high-64 halves
    float4 bias_lo = make_float4(0,0,0,0), bias_hi = make_float4(0,0,0,0);
    if (bias) {
        bias_lo = *(const float4*)(bias + col0 + tx*4);
        bias_hi = *(const float4*)(bias + col0 + 64 + tx*4);
    }

    #pragma unroll
    for (int i = 0; i < 8; i++) {
        int r = row0 + ((i < 4) ? (ty*4 + i) : (64 + ty*4 + i - 4));
        size_t base = (size_t)r * N + col0;
        float4 lo = make_float4(acc[i][0], acc[i][1], acc[i][2], acc[i][3]);
        float4 hi = make_float4(acc[i][4], acc[i][5], acc[i][6], acc[i][7]);
        lo.x += bias_lo.x; lo.y += bias_lo.y; lo.z += bias_lo.z; lo.w += bias_lo.w;
        hi.x += bias_hi.x; hi.y += bias_hi.y; hi.z += bias_hi.z; hi.w += bias_hi.w;
        if (res) {
            float4 r0 = *(const float4*)(res + base + tx*4);
            float4 r1 = *(const float4*)(res + base + 64 + tx*4);
            lo.x += r0.x; lo.y += r0.y; lo.z += r0.z; lo.w += r0.w;
            hi.x += r1.x; hi.y += r1.y; hi.z += r1.z; hi.w += r1.w;
        }
        if (do_relu) {
            lo.x = fmaxf(lo.x, 0.f); lo.y = fmaxf(lo.y, 0.f);
            lo.z = fmaxf(lo.z, 0.f); lo.w = fmaxf(lo.w, 0.f);
            hi.x = fmaxf(hi.x, 0.f); hi.y = fmaxf(hi.y, 0.f);
            hi.z = fmaxf(hi.z, 0.f); hi.w = fmaxf(hi.w, 0.f);
        }
        *(float4*)(C + base + tx*4)      = lo;
        *(float4*)(C + base + 64 + tx*4) = hi;
    }
}

// ---------------- causal attention: one block per (b, h, t) ----------------
// q,k,v layout: [B*T, E], head h occupies columns h*64 .. h*64+63
__global__ __launch_bounds__(128)
void attn_kernel(const float* __restrict__ q, const float* __restrict__ k,
                 const float* __restrict__ v, float* __restrict__ o)
{
    __shared__ float s_q[DD];
    __shared__ float s_sc[TT];
    __shared__ float s_red[128];
    __shared__ float s_acc[128];
    __shared__ float s_bcast;

    int t  = blockIdx.x;
    int hh = blockIdx.y;
    int b  = blockIdx.z;
    int tid = threadIdx.x;
    int row  = b * TT + t;
    int col0 = hh * DD;
    const float scale = 0.125f;   // D^-0.5, D=64

    if (tid < DD) s_q[tid] = q[(size_t)row * EE + col0 + tid] * scale;
    __syncthreads();

    int nk = t + 1;

    // scores
    for (int kp = tid; kp < nk; kp += 128) {
        const float4* kr = (const float4*)(k + (size_t)(b*TT + kp) * EE + col0);
        const float4* qr = (const float4*)s_q;
        float dot = 0.f;
        #pragma unroll
        for (int i = 0; i < DD/4; i++) {
            float4 kv = kr[i];
            float4 qv = qr[i];
            dot += kv.x*qv.x + kv.y*qv.y + kv.z*qv.z + kv.w*qv.w;
        }
        s_sc[kp] = dot;
    }
    __syncthreads();

    // max reduce
    float lmax = -INFINITY;
    for (int kp = tid; kp < nk; kp += 128) lmax = fmaxf(lmax, s_sc[kp]);
    s_red[tid] = lmax; __syncthreads();
    for (int ofs = 64; ofs > 0; ofs >>= 1) { if (tid < ofs) s_red[tid] = fmaxf(s_red[tid], s_red[tid+ofs]); __syncthreads(); }
    if (tid == 0) s_bcast = s_red[0];
    __syncthreads();
    float mx = s_bcast;
    __syncthreads();

    // exp + sum reduce
    float lsum = 0.f;
    for (int kp = tid; kp < nk; kp += 128) {
        float e = expf(s_sc[kp] - mx);
        s_sc[kp] = e;
        lsum += e;
    }
    s_red[tid] = lsum; __syncthreads();
    for (int ofs = 64; ofs > 0; ofs >>= 1) { if (tid < ofs) s_red[tid] += s_red[tid+ofs]; __syncthreads(); }
    if (tid == 0) s_bcast = s_red[0];
    __syncthreads();
    float inv = 1.0f / s_bcast;

    // weighted sum of V: 2-way k-split across the 128 threads
    int half = tid >> 6;     // 0 or 1
    int d    = tid & 63;
    float acc = 0.f;
    for (int kp = half; kp < nk; kp += 2)
        acc += s_sc[kp] * v[(size_t)(b*TT + kp) * EE + col0 + d];
    s_acc[tid] = acc;
    __syncthreads();
    if (tid < DD)
        o[(size_t)row * EE + col0 + tid] = (s_acc[tid] + s_acc[tid + 64]) * inv;
}

// ---------------- host: full forward pass ----------------
extern "C" void kernel_launch(void* const* d_in, const int* in_sizes, int n_in,
                              void* d_out, int out_size)
{
    (void)in_sizes; (void)n_in;
    const int*   idx    = (const int*)  d_in[0];
    const float* tok    = (const float*)d_in[1];
    const float* pos    = (const float*)d_in[2];
    const float* Wq     = (const float*)d_in[3];
    const float* Wk     = (const float*)d_in[4];
    const float* Wv     = (const float*)d_in[5];
    const float* Wproj  = (const float*)d_in[6];
    const float* bproj  = (const float*)d_in[7];
    const float* ln1g   = (const float*)d_in[8];
    const float* ln1b   = (const float*)d_in[9];
    const float* ln2g   = (const float*)d_in[10];
    const float* ln2b   = (const float*)d_in[11];
    const float* W1     = (const float*)d_in[12];
    const float* b1     = (const float*)d_in[13];
    const float* W2     = (const float*)d_in[14];
    const float* b2     = (const float*)d_in[15];
    const float* lnfg   = (const float*)d_in[16];
    const float* lnfb   = (const float*)d_in[17];
    const float* Wlm    = (const float*)d_in[18];
    const float* blm    = (const float*)d_in[19];
    float* out = (float*)d_out;
    (void)out_size;

    float *px, *ph, *pq, *pk, *pv, *po, *pf;
    cudaGetSymbolAddress((void**)&px, g_x);
    cudaGetSymbolAddress((void**)&ph, g_h);
    cudaGetSymbolAddress((void**)&pq, g_q);
    cudaGetSymbolAddress((void**)&pk, g_k);
    cudaGetSymbolAddress((void**)&pv, g_v);
    cudaGetSymbolAddress((void**)&po, g_o);
    cudaGetSymbolAddress((void**)&pf, g_f);

    dim3 blk256(256);
    dim3 gridLN(MM);

    embed_kernel<<<MM, 256>>>(idx, tok, pos);

    dim3 gE(EE/BN,  MM/BM);   // 8  x 16
    dim3 gF(FFN/BN, MM/BM);   // 32 x 16
    dim3 gV(VV/BN,  MM/BM);   // 250 x 16
    dim3 gAttn(TT, HH, BB);

    for (int l = 0; l < LL; l++) {
        size_t offE2 = (size_t)l * EE * EE;
        size_t offEF = (size_t)l * EE * FFN;
        ln_kernel<<<gridLN, blk256>>>(px, ln1g + l*EE, ln1b + l*EE, ph);
        sgemm_kernel<<<gE, blk256>>>(ph, Wq + offE2, nullptr, nullptr, pq, MM, EE, EE, 0);
        sgemm_kernel<<<gE, blk256>>>(ph, Wk + offE2, nullptr, nullptr, pk, MM, EE, EE, 0);
        sgemm_kernel<<<gE, blk256>>>(ph, Wv + offE2, nullptr, nullptr, pv, MM, EE, EE, 0);
        attn_kernel<<<gAttn, 128>>>(pq, pk, pv, po);
        sgemm_kernel<<<gE, blk256>>>(po, Wproj + offE2, bproj + l*EE, px, px, MM, EE, EE, 0);
        ln_kernel<<<gridLN, blk256>>>(px, ln2g + l*EE, ln2b + l*EE, ph);
        sgemm_kernel<<<gF, blk256>>>(ph, W1 + offEF, b1 + (size_t)l*FFN, nullptr, pf, MM, FFN, EE, 1);
        sgemm_kernel<<<gE, blk256>>>(pf, W2 + offEF, b2 + l*EE, px, px, MM, EE, FFN, 0);
    }

    ln_kernel<<<gridLN, blk256>>>(px, lnfg, lnfb, ph);
    sgemm_kernel<<<gV, blk256>>>(ph, Wlm, blm, nullptr, out, MM, VV, EE, 0);
}

// round 4
// speedup vs baseline: 1.5744x; 1.5744x over previous
#include <cuda_runtime.h>
#include <cuda_bf16.h>
#include <stdint.h>
#include <math.h>

// ---------------- problem constants ----------------
#define BB   2
#define TT   1024
#define EE   1024
#define HH   16
#define DD   64
#define FFN  4096
#define VV   32000
#define LL   6
#define MM   (BB*TT)          // 2048 rows

// ---------------- scratch (device globals; no allocation allowed) ----------
__device__ float g_x[MM*EE];
__device__ float g_h[MM*EE];
__device__ float g_q[MM*EE];
__device__ float g_k[MM*EE];
__device__ float g_v[MM*EE];
__device__ float g_o[MM*EE];
__device__ float g_f[MM*FFN];

// ---------------- embedding: x = tok_emb[idx] + pos_emb[t] ----------------
__global__ void embed_kernel(const int* __restrict__ idx,
                             const float* __restrict__ tok,
                             const float* __restrict__ pos)
{
    int row = blockIdx.x;              // 0..2047
    int t   = row & (TT-1);
    int tokid = idx[row];
    const float4* t4 = (const float4*)(tok + (size_t)tokid * EE);
    const float4* p4 = (const float4*)(pos + (size_t)t * EE);
    float4* x4 = (float4*)(g_x + (size_t)row * EE);
    int j = threadIdx.x;               // 256 threads * 4 floats = 1024
    float4 a = t4[j], b = p4[j];
    a.x += b.x; a.y += b.y; a.z += b.z; a.w += b.w;
    x4[j] = a;
}

// ---------------- layernorm over E=1024, 256 threads/row ----------------
__global__ void ln_kernel(const float* __restrict__ x,
                          const float* __restrict__ g,
                          const float* __restrict__ b,
                          float* __restrict__ y)
{
    __shared__ float red[256];
    __shared__ float s_mu, s_inv;
    int row = blockIdx.x;
    int tid = threadIdx.x;
    const float4* xr = (const float4*)(x + (size_t)row * EE);
    float4 xv = xr[tid];

    float s = xv.x + xv.y + xv.z + xv.w;
    red[tid] = s; __syncthreads();
    for (int o = 128; o > 0; o >>= 1) { if (tid < o) red[tid] += red[tid+o]; __syncthreads(); }
    if (tid == 0) s_mu = red[0] * (1.0f/EE);
    __syncthreads();
    float mu = s_mu;

    float d0 = xv.x-mu, d1 = xv.y-mu, d2 = xv.z-mu, d3 = xv.w-mu;
    s = d0*d0 + d1*d1 + d2*d2 + d3*d3;
    __syncthreads();
    red[tid] = s; __syncthreads();
    for (int o = 128; o > 0; o >>= 1) { if (tid < o) red[tid] += red[tid+o]; __syncthreads(); }
    if (tid == 0) s_inv = rsqrtf(red[0] * (1.0f/EE) + 1e-5f);
    __syncthreads();
    float inv = s_inv;

    float4 gv = ((const float4*)g)[tid];
    float4 bv = ((const float4*)b)[tid];
    float4 out;
    out.x = d0*inv*gv.x + bv.x;
    out.y = d1*inv*gv.y + bv.y;
    out.z = d2*inv*gv.z + bv.z;
    out.w = d3*inv*gv.w + bv.w;
    ((float4*)(y + (size_t)row * EE))[tid] = out;
}

// ---------------- TF32 tensor-core GEMM ------------------------------------
// C[M,N] = A[M,K] @ W[K,N] (+bias[N]) (+res[M,N]) (relu)
// BM=128, BN=64, BK=16, 256 threads = 8 warps, warp tile 32x32,
// mma.sync.aligned.m16n8k8.row.col.f32.tf32.tf32.f32
#define BM 128
#define BN 64
#define BKK 16
#define APAD 20   // As row pitch (uint32)
#define BPAD 72   // Bs row pitch (uint32)

__device__ __forceinline__ uint32_t f2tf32(float f) {
    uint32_t r;
    asm("cvt.rna.tf32.f32 %0, %1;" : "=r"(r) : "f"(f));
    return r;
}

__device__ __forceinline__ void mma_tf32(float c[4], uint32_t a0, uint32_t a1,
                                         uint32_t a2, uint32_t a3,
                                         uint32_t b0, uint32_t b1) {
    asm volatile(
        "mma.sync.aligned.m16n8k8.row.col.f32.tf32.tf32.f32 "
        "{%0,%1,%2,%3}, {%4,%5,%6,%7}, {%8,%9}, {%0,%1,%2,%3};"
        : "+f"(c[0]), "+f"(c[1]), "+f"(c[2]), "+f"(c[3])
        : "r"(a0), "r"(a1), "r"(a2), "r"(a3), "r"(b0), "r"(b1));
}

__global__ __launch_bounds__(256)
void tgemm_kernel(const float* __restrict__ A, const float* __restrict__ W,
                  const float* __restrict__ bias, const float* __restrict__ res,
                  float* __restrict__ C, int M, int N, int K, int do_relu)
{
    __shared__ uint32_t As[BM][APAD];   // [row][k], k pitch 20
    __shared__ uint32_t Bs[BKK][BPAD];  // [k][n],  n pitch 72

    int tid  = threadIdx.x;
    int lane = tid & 31;
    int warp = tid >> 5;
    int warpM = (warp & 3) * 32;        // 0,32,64,96
    int warpN = (warp >> 2) * 32;       // 0,32

    int row0 = blockIdx.y * BM;
    int col0 = blockIdx.x * BN;

    float acc[2][4][4];
    #pragma unroll
    for (int mi = 0; mi < 2; mi++)
        #pragma unroll
        for (int ni = 0; ni < 4; ni++)
            #pragma unroll
            for (int r = 0; r < 4; r++) acc[mi][ni][r] = 0.f;

    // global load indices
    int a_r  = tid >> 2;                // 0..63
    int a_c4 = (tid & 3) * 4;           // 0,4,8,12
    int b_r  = tid >> 4;                // 0..15
    int b_c4 = (tid & 15) * 4;          // 0..60

    const float* Abase = A + (size_t)(row0 + a_r) * K + a_c4;
    const float* Wbase = W + (size_t)b_r * N + col0 + b_c4;

    for (int k0 = 0; k0 < K; k0 += BKK) {
        // load A tile: 128x16 (two 64-row halves per thread)
        #pragma unroll
        for (int h = 0; h < 2; h++) {
            float4 v = *(const float4*)(Abase + (size_t)h * 64 * K + k0);
            uint32_t* d = &As[a_r + h*64][a_c4];
            d[0] = f2tf32(v.x); d[1] = f2tf32(v.y);
            d[2] = f2tf32(v.z); d[3] = f2tf32(v.w);
        }
        // load B tile: 16x64
        {
            float4 v = *(const float4*)(Wbase + (size_t)k0 * N);
            uint32_t* d = &Bs[b_r][b_c4];
            d[0] = f2tf32(v.x); d[1] = f2tf32(v.y);
            d[2] = f2tf32(v.z); d[3] = f2tf32(v.w);
        }
        __syncthreads();

        #pragma unroll
        for (int kk = 0; kk < 2; kk++) {
            int kb = kk * 8;
            uint32_t a[2][4];
            #pragma unroll
            for (int mi = 0; mi < 2; mi++) {
                int rb = warpM + mi*16 + (lane >> 2);
                int cb = kb + (lane & 3);
                a[mi][0] = As[rb    ][cb    ];
                a[mi][1] = As[rb + 8][cb    ];
                a[mi][2] = As[rb    ][cb + 4];
                a[mi][3] = As[rb + 8][cb + 4];
            }
            uint32_t b[4][2];
            #pragma unroll
            for (int ni = 0; ni < 4; ni++) {
                int nb = warpN + ni*8 + (lane >> 2);
                int kr = kb + (lane & 3);
                b[ni][0] = Bs[kr    ][nb];
                b[ni][1] = Bs[kr + 4][nb];
            }
            #pragma unroll
            for (int mi = 0; mi < 2; mi++)
                #pragma unroll
                for (int ni = 0; ni < 4; ni++)
                    mma_tf32(acc[mi][ni], a[mi][0], a[mi][1], a[mi][2], a[mi][3],
                             b[ni][0], b[ni][1]);
        }
        __syncthreads();
    }

    // epilogue
    #pragma unroll
    for (int mi = 0; mi < 2; mi++) {
        #pragma unroll
        for (int ni = 0; ni < 4; ni++) {
            int r0 = row0 + warpM + mi*16 + (lane >> 2);
            int c  = col0 + warpN + ni*8 + (lane & 3)*2;
            float2 lo = make_float2(acc[mi][ni][0], acc[mi][ni][1]);
            float2 hi = make_float2(acc[mi][ni][2], acc[mi][ni][3]);
            if (bias) {
                float2 bv = *(const float2*)(bias + c);
                lo.x += bv.x; lo.y += bv.y;
                hi.x += bv.x; hi.y += bv.y;
            }
            size_t o0 = (size_t)r0 * N + c;
            size_t o1 = (size_t)(r0 + 8) * N + c;
            if (res) {
                float2 r0v = *(const float2*)(res + o0);
                float2 r1v = *(const float2*)(res + o1);
                lo.x += r0v.x; lo.y += r0v.y;
                hi.x += r1v.x; hi.y += r1v.y;
            }
            if (do_relu) {
                lo.x = fmaxf(lo.x, 0.f); lo.y = fmaxf(lo.y, 0.f);
                hi.x = fmaxf(hi.x, 0.f); hi.y = fmaxf(hi.y, 0.f);
            }
            *(float2*)(C + o0) = lo;
            *(float2*)(C + o1) = hi;
        }
    }
}

// ---------------- causal attention: one block per (b, h, t) ----------------
__global__ __launch_bounds__(128)
void attn_kernel(const float* __restrict__ q, const float* __restrict__ k,
                 const float* __restrict__ v, float* __restrict__ o)
{
    __shared__ float s_q[DD];
    __shared__ float s_sc[TT];
    __shared__ float s_red[128];
    __shared__ float s_acc[128];
    __shared__ float s_bcast;

    int t  = blockIdx.x;
    int hh = blockIdx.y;
    int b  = blockIdx.z;
    int tid = threadIdx.x;
    int row  = b * TT + t;
    int col0 = hh * DD;
    const float scale = 0.125f;

    if (tid < DD) s_q[tid] = q[(size_t)row * EE + col0 + tid] * scale;
    __syncthreads();

    int nk = t + 1;

    for (int kp = tid; kp < nk; kp += 128) {
        const float4* kr = (const float4*)(k + (size_t)(b*TT + kp) * EE + col0);
        const float4* qr = (const float4*)s_q;
        float dot = 0.f;
        #pragma unroll
        for (int i = 0; i < DD/4; i++) {
            float4 kv = kr[i];
            float4 qv = qr[i];
            dot += kv.x*qv.x + kv.y*qv.y + kv.z*qv.z + kv.w*qv.w;
        }
        s_sc[kp] = dot;
    }
    __syncthreads();

    float lmax = -INFINITY;
    for (int kp = tid; kp < nk; kp += 128) lmax = fmaxf(lmax, s_sc[kp]);
    s_red[tid] = lmax; __syncthreads();
    for (int ofs = 64; ofs > 0; ofs >>= 1) { if (tid < ofs) s_red[tid] = fmaxf(s_red[tid], s_red[tid+ofs]); __syncthreads(); }
    if (tid == 0) s_bcast = s_red[0];
    __syncthreads();
    float mx = s_bcast;
    __syncthreads();

    float lsum = 0.f;
    for (int kp = tid; kp < nk; kp += 128) {
        float e = expf(s_sc[kp] - mx);
        s_sc[kp] = e;
        lsum += e;
    }
    s_red[tid] = lsum; __syncthreads();
    for (int ofs = 64; ofs > 0; ofs >>= 1) { if (tid < ofs) s_red[tid] += s_red[tid+ofs]; __syncthreads(); }
    if (tid == 0) s_bcast = s_red[0];
    __syncthreads();
    float inv = 1.0f / s_bcast;

    int half = tid >> 6;
    int d    = tid & 63;
    float acc = 0.f;
    for (int kp = half; kp < nk; kp += 2)
        acc += s_sc[kp] * v[(size_t)(b*TT + kp) * EE + col0 + d];
    s_acc[tid] = acc;
    __syncthreads();
    if (tid < DD)
        o[(size_t)row * EE + col0 + tid] = (s_acc[tid] + s_acc[tid + 64]) * inv;
}

// ---------------- host: full forward pass ----------------
extern "C" void kernel_launch(void* const* d_in, const int* in_sizes, int n_in,
                              void* d_out, int out_size)
{
    (void)in_sizes; (void)n_in;
    const int*   idx    = (const int*)  d_in[0];
    const float* tok    = (const float*)d_in[1];
    const float* pos    = (const float*)d_in[2];
    const float* Wq     = (const float*)d_in[3];
    const float* Wk     = (const float*)d_in[4];
    const float* Wv     = (const float*)d_in[5];
    const float* Wproj  = (const float*)d_in[6];
    const float* bproj  = (const float*)d_in[7];
    const float* ln1g   = (const float*)d_in[8];
    const float* ln1b   = (const float*)d_in[9];
    const float* ln2g   = (const float*)d_in[10];
    const float* ln2b   = (const float*)d_in[11];
    const float* W1     = (const float*)d_in[12];
    const float* b1     = (const float*)d_in[13];
    const float* W2     = (const float*)d_in[14];
    const float* b2     = (const float*)d_in[15];
    const float* lnfg   = (const float*)d_in[16];
    const float* lnfb   = (const float*)d_in[17];
    const float* Wlm    = (const float*)d_in[18];
    const float* blm    = (const float*)d_in[19];
    float* out = (float*)d_out;
    (void)out_size;

    float *px, *ph, *pq, *pk, *pv, *po, *pf;
    cudaGetSymbolAddress((void**)&px, g_x);
    cudaGetSymbolAddress((void**)&ph, g_h);
    cudaGetSymbolAddress((void**)&pq, g_q);
    cudaGetSymbolAddress((void**)&pk, g_k);
    cudaGetSymbolAddress((void**)&pv, g_v);
    cudaGetSymbolAddress((void**)&po, g_o);
    cudaGetSymbolAddress((void**)&pf, g_f);

    dim3 blk256(256);
    dim3 gridLN(MM);

    embed_kernel<<<MM, 256>>>(idx, tok, pos);

    dim3 gE(EE/BN,  MM/BM);   // 16 x 16
    dim3 gF(FFN/BN, MM/BM);   // 64 x 16
    dim3 gV(VV/BN,  MM/BM);   // 500 x 16
    dim3 gAttn(TT, HH, BB);

    for (int l = 0; l < LL; l++) {
        size_t offE2 = (size_t)l * EE * EE;
        size_t offEF = (size_t)l * EE * FFN;
        ln_kernel<<<gridLN, blk256>>>(px, ln1g + l*EE, ln1b + l*EE, ph);
        tgemm_kernel<<<gE, blk256>>>(ph, Wq + offE2, nullptr, nullptr, pq, MM, EE, EE, 0);
        tgemm_kernel<<<gE, blk256>>>(ph, Wk + offE2, nullptr, nullptr, pk, MM, EE, EE, 0);
        tgemm_kernel<<<gE, blk256>>>(ph, Wv + offE2, nullptr, nullptr, pv, MM, EE, EE, 0);
        attn_kernel<<<gAttn, 128>>>(pq, pk, pv, po);
        tgemm_kernel<<<gE, blk256>>>(po, Wproj + offE2, bproj + l*EE, px, px, MM, EE, EE, 0);
        ln_kernel<<<gridLN, blk256>>>(px, ln2g + l*EE, ln2b + l*EE, ph);
        tgemm_kernel<<<gF, blk256>>>(ph, W1 + offEF, b1 + (size_t)l*FFN, nullptr, pf, MM, FFN, EE, 1);
        tgemm_kernel<<<gE, blk256>>>(pf, W2 + offEF, b2 + l*EE, px, px, MM, EE, FFN, 0);
    }

    ln_kernel<<<gridLN, blk256>>>(px, lnfg, lnfb, ph);
    tgemm_kernel<<<gV, blk256>>>(ph, Wlm, blm, nullptr, out, MM, VV, EE, 0);
}

// round 6
// speedup vs baseline: 1.9807x; 1.2581x over previous
#include <cuda_runtime.h>
#include <cuda_bf16.h>
#include <stdint.h>
#include <math.h>

// ---------------- problem constants ----------------
#define BB   2
#define TT   1024
#define EE   1024
#define HH   16
#define DD   64
#define FFN  4096
#define VV   32000
#define LL   6
#define MM   (BB*TT)          // 2048 rows

// ---------------- scratch (device globals; no allocation allowed) ----------
__device__ float g_x[MM*EE];
__device__ float g_h[MM*EE];
__device__ float g_q[MM*EE];
__device__ float g_k[MM*EE];
__device__ float g_v[MM*EE];
__device__ float g_o[MM*EE];
__device__ float g_f[MM*FFN];

// ---------------- embedding ----------------
__global__ void embed_kernel(const int* __restrict__ idx,
                             const float* __restrict__ tok,
                             const float* __restrict__ pos)
{
    int row = blockIdx.x;
    int t   = row & (TT-1);
    int tokid = idx[row];
    const float4* t4 = (const float4*)(tok + (size_t)tokid * EE);
    const float4* p4 = (const float4*)(pos + (size_t)t * EE);
    float4* x4 = (float4*)(g_x + (size_t)row * EE);
    int j = threadIdx.x;
    float4 a = t4[j], b = p4[j];
    a.x += b.x; a.y += b.y; a.z += b.z; a.w += b.w;
    x4[j] = a;
}

// ---------------- layernorm ----------------
__global__ void ln_kernel(const float* __restrict__ x,
                          const float* __restrict__ g,
                          const float* __restrict__ b,
                          float* __restrict__ y)
{
    __shared__ float red[256];
    __shared__ float s_mu, s_inv;
    int row = blockIdx.x;
    int tid = threadIdx.x;
    const float4* xr = (const float4*)(x + (size_t)row * EE);
    float4 xv = xr[tid];

    float s = xv.x + xv.y + xv.z + xv.w;
    red[tid] = s; __syncthreads();
    for (int o = 128; o > 0; o >>= 1) { if (tid < o) red[tid] += red[tid+o]; __syncthreads(); }
    if (tid == 0) s_mu = red[0] * (1.0f/EE);
    __syncthreads();
    float mu = s_mu;

    float d0 = xv.x-mu, d1 = xv.y-mu, d2 = xv.z-mu, d3 = xv.w-mu;
    s = d0*d0 + d1*d1 + d2*d2 + d3*d3;
    __syncthreads();
    red[tid] = s; __syncthreads();
    for (int o = 128; o > 0; o >>= 1) { if (tid < o) red[tid] += red[tid+o]; __syncthreads(); }
    if (tid == 0) s_inv = rsqrtf(red[0] * (1.0f/EE) + 1e-5f);
    __syncthreads();
    float inv = s_inv;

    float4 gv = ((const float4*)g)[tid];
    float4 bv = ((const float4*)b)[tid];
    float4 out;
    out.x = d0*inv*gv.x + bv.x;
    out.y = d1*inv*gv.y + bv.y;
    out.z = d2*inv*gv.z + bv.z;
    out.w = d3*inv*gv.w + bv.w;
    ((float4*)(y + (size_t)row * EE))[tid] = out;
}

// ---------------- TF32 tensor-core GEMM, double-buffered -------------------
// C[M,N] = A[M,K] @ W[K,N] (+bias) (+res) (relu)
// BM=128, BN=128, BK=16, 256 threads = 8 warps (4 along M, 2 along N),
// warp tile 32x64, mma.m16n8k8 tf32.
#define BM 128
#define BN 128
#define BKK 16
#define APAD 20    // As k-pitch (uint32)
#define BPAD 136   // Bs n-pitch (uint32)

__device__ __forceinline__ uint32_t f2tf32(float f) {
    uint32_t r;
    asm("cvt.rna.tf32.f32 %0, %1;" : "=r"(r) : "f"(f));
    return r;
}

__device__ __forceinline__ void mma_tf32(float c[4], uint32_t a0, uint32_t a1,
                                         uint32_t a2, uint32_t a3,
                                         uint32_t b0, uint32_t b1) {
    asm volatile(
        "mma.sync.aligned.m16n8k8.row.col.f32.tf32.tf32.f32 "
        "{%0,%1,%2,%3}, {%4,%5,%6,%7}, {%8,%9}, {%0,%1,%2,%3};"
        : "+f"(c[0]), "+f"(c[1]), "+f"(c[2]), "+f"(c[3])
        : "r"(a0), "r"(a1), "r"(a2), "r"(a3), "r"(b0), "r"(b1));
}

__global__ __launch_bounds__(256, 2)
void tgemm_kernel(const float* __restrict__ A, const float* __restrict__ W,
                  const float* __restrict__ bias, const float* __restrict__ res,
                  float* __restrict__ C, int M, int N, int K, int do_relu)
{
    __shared__ uint32_t As[2][BM][APAD];
    __shared__ uint32_t Bs[2][BKK][BPAD];

    int tid  = threadIdx.x;
    int lane = tid & 31;
    int warp = tid >> 5;
    int warpM = (warp & 3) * 32;        // 0,32,64,96
    int warpN = (warp >> 2) * 64;       // 0,64

    int row0 = blockIdx.y * BM;
    int col0 = blockIdx.x * BN;

    float acc[2][8][4];
    #pragma unroll
    for (int mi = 0; mi < 2; mi++)
        #pragma unroll
        for (int ni = 0; ni < 8; ni++)
            #pragma unroll
            for (int r = 0; r < 4; r++) acc[mi][ni][r] = 0.f;

    int a_r  = tid >> 2;                // 0..63
    int a_c4 = (tid & 3) * 4;           // 0,4,8,12
    int b_r  = tid >> 4;                // 0..15
    int b_c8 = (tid & 15) * 8;          // 0..120

    const float* Abase = A + (size_t)(row0 + a_r) * K + a_c4;
    const float* Wbase = W + (size_t)b_r * N + col0 + b_c8;

    // prologue: tile 0 -> buffer 0
    {
        float4 a0 = *(const float4*)(Abase);
        float4 a1 = *(const float4*)(Abase + (size_t)64 * K);
        float4 b0 = *(const float4*)(Wbase);
        float4 b1 = *(const float4*)(Wbase + 4);
        uint32_t* d0 = &As[0][a_r][a_c4];
        d0[0]=f2tf32(a0.x); d0[1]=f2tf32(a0.y); d0[2]=f2tf32(a0.z); d0[3]=f2tf32(a0.w);
        uint32_t* d1 = &As[0][a_r + 64][a_c4];
        d1[0]=f2tf32(a1.x); d1[1]=f2tf32(a1.y); d1[2]=f2tf32(a1.z); d1[3]=f2tf32(a1.w);
        uint32_t* e = &Bs[0][b_r][b_c8];
        e[0]=f2tf32(b0.x); e[1]=f2tf32(b0.y); e[2]=f2tf32(b0.z); e[3]=f2tf32(b0.w);
        e[4]=f2tf32(b1.x); e[5]=f2tf32(b1.y); e[6]=f2tf32(b1.z); e[7]=f2tf32(b1.w);
    }
    __syncthreads();

    int cur = 0;
    for (int k0 = 0; k0 < K; k0 += BKK, cur ^= 1) {
        int kn = k0 + BKK;
        bool has_next = kn < K;
        float4 na0, na1, nb0, nb1;
        if (has_next) {
            na0 = *(const float4*)(Abase + kn);
            na1 = *(const float4*)(Abase + (size_t)64 * K + kn);
            nb0 = *(const float4*)(Wbase + (size_t)kn * N);
            nb1 = *(const float4*)(Wbase + (size_t)kn * N + 4);
        }

        #pragma unroll
        for (int kk = 0; kk < 2; kk++) {
            int kb = kk * 8;
            uint32_t a[2][4];
            #pragma unroll
            for (int mi = 0; mi < 2; mi++) {
                int rb = warpM + mi*16 + (lane >> 2);
                int cb = kb + (lane & 3);
                a[mi][0] = As[cur][rb    ][cb    ];
                a[mi][1] = As[cur][rb + 8][cb    ];
                a[mi][2] = As[cur][rb    ][cb + 4];
                a[mi][3] = As[cur][rb + 8][cb + 4];
            }
            uint32_t b[8][2];
            #pragma unroll
            for (int ni = 0; ni < 8; ni++) {
                int nb_ = warpN + ni*8 + (lane >> 2);
                int kr  = kb + (lane & 3);
                b[ni][0] = Bs[cur][kr    ][nb_];
                b[ni][1] = Bs[cur][kr + 4][nb_];
            }
            #pragma unroll
            for (int mi = 0; mi < 2; mi++)
                #pragma unroll
                for (int ni = 0; ni < 8; ni++)
                    mma_tf32(acc[mi][ni], a[mi][0], a[mi][1], a[mi][2], a[mi][3],
                             b[ni][0], b[ni][1]);
        }

        if (has_next) {
            int nxt = cur ^ 1;
            uint32_t* d0 = &As[nxt][a_r][a_c4];
            d0[0]=f2tf32(na0.x); d0[1]=f2tf32(na0.y); d0[2]=f2tf32(na0.z); d0[3]=f2tf32(na0.w);
            uint32_t* d1 = &As[nxt][a_r + 64][a_c4];
            d1[0]=f2tf32(na1.x); d1[1]=f2tf32(na1.y); d1[2]=f2tf32(na1.z); d1[3]=f2tf32(na1.w);
            uint32_t* e = &Bs[nxt][b_r][b_c8];
            e[0]=f2tf32(nb0.x); e[1]=f2tf32(nb0.y); e[2]=f2tf32(nb0.z); e[3]=f2tf32(nb0.w);
            e[4]=f2tf32(nb1.x); e[5]=f2tf32(nb1.y); e[6]=f2tf32(nb1.z); e[7]=f2tf32(nb1.w);
        }
        __syncthreads();
    }

    // epilogue
    #pragma unroll
    for (int mi = 0; mi < 2; mi++) {
        #pragma unroll
        for (int ni = 0; ni < 8; ni++) {
            int r0 = row0 + warpM + mi*16 + (lane >> 2);
            int c  = col0 + warpN + ni*8 + (lane & 3)*2;
            float2 lo = make_float2(acc[mi][ni][0], acc[mi][ni][1]);
            float2 hi = make_float2(acc[mi][ni][2], acc[mi][ni][3]);
            if (bias) {
                float2 bv = *(const float2*)(bias + c);
                lo.x += bv.x; lo.y += bv.y;
                hi.x += bv.x; hi.y += bv.y;
            }
            size_t o0 = (size_t)r0 * N + c;
            size_t o1 = (size_t)(r0 + 8) * N + c;
            if (res) {
                float2 r0v = *(const float2*)(res + o0);
                float2 r1v = *(const float2*)(res + o1);
                lo.x += r0v.x; lo.y += r0v.y;
                hi.x += r1v.x; hi.y += r1v.y;
            }
            if (do_relu) {
                lo.x = fmaxf(lo.x, 0.f); lo.y = fmaxf(lo.y, 0.f);
                hi.x = fmaxf(hi.x, 0.f); hi.y = fmaxf(hi.y, 0.f);
            }
            *(float2*)(C + o0) = lo;
            *(float2*)(C + o1) = hi;
        }
    }
}

// ---------------- flash-style causal attention ------------------------------
// block = (qtile of 128 rows, head, batch); 128 threads; thread owns 1 q row.
// K/V tiles of 64 rows staged in SMEM; online softmax; q,o in registers.
#define KTILE 64
#define KVPITCH 68

__global__ __launch_bounds__(128)
void attn_kernel(const float* __restrict__ q, const float* __restrict__ k,
                 const float* __restrict__ v, float* __restrict__ o)
{
    __shared__ float Ks[KTILE][KVPITCH];
    __shared__ float Vs[KTILE][KVPITCH];

    int qt  = blockIdx.x;      // 0..7
    int hh  = blockIdx.y;
    int b   = blockIdx.z;
    int tid = threadIdx.x;     // 0..127
    int r    = qt * 128 + tid;        // query row within sequence
    int grow = b * TT + r;
    int col0 = hh * DD;

    float4 q4[16], o4[16];
    const float4* qp = (const float4*)(q + (size_t)grow * EE + col0);
    #pragma unroll
    for (int i = 0; i < 16; i++) {
        float4 t = qp[i];
        t.x *= 0.125f; t.y *= 0.125f; t.z *= 0.125f; t.w *= 0.125f;
        q4[i] = t;
        o4[i] = make_float4(0.f, 0.f, 0.f, 0.f);
    }
    float m = -INFINITY, l = 0.f;

    int ntiles = (qt * 128 + 128) / KTILE;   // 2*(qt+1)
    int tr = tid >> 1;                       // 0..63
    int tc = (tid & 1) * 32;                 // 0 or 32

    for (int kt = 0; kt < ntiles; kt++) {
        int krow = b * TT + kt * KTILE + tr;
        const float4* ksrc = (const float4*)(k + (size_t)krow * EE + col0 + tc);
        const float4* vsrc = (const float4*)(v + (size_t)krow * EE + col0 + tc);
        float4* kdst = (float4*)&Ks[tr][tc];
        float4* vdst = (float4*)&Vs[tr][tc];
        #pragma unroll
        for (int i = 0; i < 8; i++) { kdst[i] = ksrc[i]; vdst[i] = vsrc[i]; }
        __syncthreads();

        int jmax = r - kt * KTILE + 1;
        if (jmax > KTILE) jmax = KTILE;
        for (int j = 0; j < jmax; j++) {
            const float4* kr4 = (const float4*)&Ks[j][0];
            float s0 = 0.f, s1 = 0.f, s2 = 0.f, s3 = 0.f;
            #pragma unroll
            for (int i = 0; i < 16; i++) {
                float4 kv = kr4[i];
                s0 += q4[i].x * kv.x; s1 += q4[i].y * kv.y;
                s2 += q4[i].z * kv.z; s3 += q4[i].w * kv.w;
            }
            float s = (s0 + s1) + (s2 + s3);
            float mn = fmaxf(m, s);
            float corr = expf(m - mn);
            float p = expf(s - mn);
            l = l * corr + p;
            m = mn;
            const float4* vr4 = (const float4*)&Vs[j][0];
            #pragma unroll
            for (int i = 0; i < 16; i++) {
                float4 vv = vr4[i];
                o4[i].x = o4[i].x * corr + p * vv.x;
                o4[i].y = o4[i].y * corr + p * vv.y;
                o4[i].z = o4[i].z * corr + p * vv.z;
                o4[i].w = o4[i].w * corr + p * vv.w;
            }
        }
        __syncthreads();
    }

    float inv = 1.f / l;
    float4* op = (float4*)(o + (size_t)grow * EE + col0);
    #pragma unroll
    for (int i = 0; i < 16; i++) {
        float4 t = o4[i];
        t.x *= inv; t.y *= inv; t.z *= inv; t.w *= inv;
        op[i] = t;
    }
}

// ---------------- host: full forward pass ----------------
extern "C" void kernel_launch(void* const* d_in, const int* in_sizes, int n_in,
                              void* d_out, int out_size)
{
    (void)in_sizes; (void)n_in;
    const int*   idx    = (const int*)  d_in[0];
    const float* tok    = (const float*)d_in[1];
    const float* pos    = (const float*)d_in[2];
    const float* Wq     = (const float*)d_in[3];
    const float* Wk     = (const float*)d_in[4];
    const float* Wv     = (const float*)d_in[5];
    const float* Wproj  = (const float*)d_in[6];
    const float* bproj  = (const float*)d_in[7];
    const float* ln1g   = (const float*)d_in[8];
    const float* ln1b   = (const float*)d_in[9];
    const float* ln2g   = (const float*)d_in[10];
    const float* ln2b   = (const float*)d_in[11];
    const float* W1     = (const float*)d_in[12];
    const float* b1     = (const float*)d_in[13];
    const float* W2     = (const float*)d_in[14];
    const float* b2     = (const float*)d_in[15];
    const float* lnfg   = (const float*)d_in[16];
    const float* lnfb   = (const float*)d_in[17];
    const float* Wlm    = (const float*)d_in[18];
    const float* blm    = (const float*)d_in[19];
    float* out = (float*)d_out;
    (void)out_size;

    float *px, *ph, *pq, *pk, *pv, *po, *pf;
    cudaGetSymbolAddress((void**)&px, g_x);
    cudaGetSymbolAddress((void**)&ph, g_h);
    cudaGetSymbolAddress((void**)&pq, g_q);
    cudaGetSymbolAddress((void**)&pk, g_k);
    cudaGetSymbolAddress((void**)&pv, g_v);
    cudaGetSymbolAddress((void**)&po, g_o);
    cudaGetSymbolAddress((void**)&pf, g_f);

    dim3 blk256(256);
    dim3 gridLN(MM);

    embed_kernel<<<MM, 256>>>(idx, tok, pos);

    dim3 gE(EE/BN,  MM/BM);   // 8   x 16
    dim3 gF(FFN/BN, MM/BM);   // 32  x 16
    dim3 gV(VV/BN,  MM/BM);   // 250 x 16
    dim3 gAttn(TT/128, HH, BB);

    for (int l = 0; l < LL; l++) {
        size_t offE2 = (size_t)l * EE * EE;
        size_t offEF = (size_t)l * EE * FFN;
        ln_kernel<<<gridLN, blk256>>>(px, ln1g + l*EE, ln1b + l*EE, ph);
        tgemm_kernel<<<gE, blk256>>>(ph, Wq + offE2, nullptr, nullptr, pq, MM, EE, EE, 0);
        tgemm_kernel<<<gE, blk256>>>(ph, Wk + offE2, nullptr, nullptr, pk, MM, EE, EE, 0);
        tgemm_kernel<<<gE, blk256>>>(ph, Wv + offE2, nullptr, nullptr, pv, MM, EE, EE, 0);
        attn_kernel<<<gAttn, 128>>>(pq, pk, pv, po);
        tgemm_kernel<<<gE, blk256>>>(po, Wproj + offE2, bproj + l*EE, px, px, MM, EE, EE, 0);
        ln_kernel<<<gridLN, blk256>>>(px, ln2g + l*EE, ln2b + l*EE, ph);
        tgemm_kernel<<<gF, blk256>>>(ph, W1 + offEF, b1 + (size_t)l*FFN, nullptr, pf, MM, FFN, EE, 1);
        tgemm_kernel<<<gE, blk256>>>(pf, W2 + offEF, b2 + l*EE, px, px, MM, EE, FFN, 0);
    }

    ln_kernel<<<gridLN, blk256>>>(px, lnfg, lnfb, ph);
    tgemm_kernel<<<gV, blk256>>>(ph, Wlm, blm, nullptr, out, MM, VV, EE, 0);
}

// round 8
// speedup vs baseline: 3.1327x; 1.5816x over previous
#include <cuda_runtime.h>
#include <cuda_bf16.h>
#include <stdint.h>
#include <math.h>

// ---------------- problem constants ----------------
#define BB   2
#define TT   1024
#define EE   1024
#define HH   16
#define DD   64
#define FFN  4096
#define VV   32000
#define LL   6
#define MM   (BB*TT)          // 2048 rows

#define S4   (LL*EE*EE)       // 6291456
#define SF   (LL*EE*FFN)      // 25165824
#define SLM  (EE*VV)          // 32768000

// ---------------- scratch (device globals; no allocation allowed) ----------
__device__ float g_x[MM*EE];
__device__ float g_h[MM*EE];
__device__ float g_q[MM*EE];
__device__ float g_k[MM*EE];
__device__ float g_v[MM*EE];
__device__ float g_o[MM*EE];
__device__ float g_f[MM*FFN];
// tf32-pre-rounded weights
__device__ float g_cwq[S4];
__device__ float g_cwk[S4];
__device__ float g_cwv[S4];
__device__ float g_cwp[S4];
__device__ float g_cw1[SF];
__device__ float g_cw2[SF];
__device__ float g_cwlm[SLM];

__device__ __forceinline__ uint32_t f2tf32(float f) {
    uint32_t r;
    asm("cvt.rna.tf32.f32 %0, %1;" : "=r"(r) : "f"(f));
    return r;
}
__device__ __forceinline__ float rnd_tf32(float f) {
    return __uint_as_float(f2tf32(f));
}

// ---------------- weight pre-rounding ----------------
__global__ void cvt_kernel(const float* __restrict__ src, float* __restrict__ dst, int n4)
{
    int i = blockIdx.x * blockDim.x + threadIdx.x;
    if (i < n4) {
        float4 v = ((const float4*)src)[i];
        float4 o;
        o.x = rnd_tf32(v.x); o.y = rnd_tf32(v.y);
        o.z = rnd_tf32(v.z); o.w = rnd_tf32(v.w);
        ((float4*)dst)[i] = o;
    }
}

// ---------------- embedding ----------------
__global__ void embed_kernel(const int* __restrict__ idx,
                             const float* __restrict__ tok,
                             const float* __restrict__ pos)
{
    int row = blockIdx.x;
    int t   = row & (TT-1);
    int tokid = idx[row];
    const float4* t4 = (const float4*)(tok + (size_t)tokid * EE);
    const float4* p4 = (const float4*)(pos + (size_t)t * EE);
    float4* x4 = (float4*)(g_x + (size_t)row * EE);
    int j = threadIdx.x;
    float4 a = t4[j], b = p4[j];
    a.x += b.x; a.y += b.y; a.z += b.z; a.w += b.w;
    x4[j] = a;
}

// ---------------- layernorm (output tf32-rounded; feeds GEMMs only) --------
__global__ void ln_kernel(const float* __restrict__ x,
                          const float* __restrict__ g,
                          const float* __restrict__ b,
                          float* __restrict__ y)
{
    __shared__ float red[256];
    __shared__ float s_mu, s_inv;
    int row = blockIdx.x;
    int tid = threadIdx.x;
    const float4* xr = (const float4*)(x + (size_t)row * EE);
    float4 xv = xr[tid];

    float s = xv.x + xv.y + xv.z + xv.w;
    red[tid] = s; __syncthreads();
    for (int o = 128; o > 0; o >>= 1) { if (tid < o) red[tid] += red[tid+o]; __syncthreads(); }
    if (tid == 0) s_mu = red[0] * (1.0f/EE);
    __syncthreads();
    float mu = s_mu;

    float d0 = xv.x-mu, d1 = xv.y-mu, d2 = xv.z-mu, d3 = xv.w-mu;
    s = d0*d0 + d1*d1 + d2*d2 + d3*d3;
    __syncthreads();
    red[tid] = s; __syncthreads();
    for (int o = 128; o > 0; o >>= 1) { if (tid < o) red[tid] += red[tid+o]; __syncthreads(); }
    if (tid == 0) s_inv = rsqrtf(red[0] * (1.0f/EE) + 1e-5f);
    __syncthreads();
    float inv = s_inv;

    float4 gv = ((const float4*)g)[tid];
    float4 bv = ((const float4*)b)[tid];
    float4 out;
    out.x = rnd_tf32(d0*inv*gv.x + bv.x);
    out.y = rnd_tf32(d1*inv*gv.y + bv.y);
    out.z = rnd_tf32(d2*inv*gv.z + bv.z);
    out.w = rnd_tf32(d3*inv*gv.w + bv.w);
    ((float4*)(y + (size_t)row * EE))[tid] = out;
}

// ---------------- TF32 tensor-core GEMM, cp.async 2-stage ------------------
// C[M,N] = A[M,K] @ W[K,N] (+bias) (+res) (relu) (round_out)
// A and W MUST be tf32-pre-rounded fp32. 256 thr = 8 warps, warp tile 32x64.
// gridDim.z selects among (W0,C0),(W1,C1),(W2,C2) for fused QKV.
#define BM 128
#define BN 128
#define BKK 16
#define APAD 20    // As k-pitch (floats)
#define BPAD 136   // Bs n-pitch (floats)
#define A_STAGE (BM*APAD*4)    // bytes per A stage
#define B_STAGE (BKK*BPAD*4)   // bytes per B stage

__device__ __forceinline__ void mma_tf32(float c[4], uint32_t a0, uint32_t a1,
                                         uint32_t a2, uint32_t a3,
                                         uint32_t b0, uint32_t b1) {
    asm volatile(
        "mma.sync.aligned.m16n8k8.row.col.f32.tf32.tf32.f32 "
        "{%0,%1,%2,%3}, {%4,%5,%6,%7}, {%8,%9}, {%0,%1,%2,%3};"
        : "+f"(c[0]), "+f"(c[1]), "+f"(c[2]), "+f"(c[3])
        : "r"(a0), "r"(a1), "r"(a2), "r"(a3), "r"(b0), "r"(b1));
}

__device__ __forceinline__ void cp_async16(uint32_t dst, const float* src) {
    asm volatile("cp.async.cg.shared.global [%0], [%1], 16;" :: "r"(dst), "l"(src));
}

__global__ __launch_bounds__(256, 2)
void tgemm_kernel(const float* __restrict__ A,
                  const float* __restrict__ W0, const float* __restrict__ W1p,
                  const float* __restrict__ W2p,
                  const float* __restrict__ bias, const float* __restrict__ res,
                  float* __restrict__ C0, float* __restrict__ C1p, float* __restrict__ C2p,
                  int M, int N, int K, int do_relu, int round_out)
{
    __shared__ float As[2][BM][APAD];
    __shared__ float Bs[2][BKK][BPAD];

    const float* W = (blockIdx.z == 0) ? W0 : ((blockIdx.z == 1) ? W1p : W2p);
    float*       C = (blockIdx.z == 0) ? C0 : ((blockIdx.z == 1) ? C1p : C2p);

    int tid  = threadIdx.x;
    int lane = tid & 31;
    int warp = tid >> 5;
    int warpM = (warp & 3) * 32;        // 0,32,64,96
    int warpN = (warp >> 2) * 64;       // 0,64

    int row0 = blockIdx.y * BM;
    int col0 = blockIdx.x * BN;

    float acc[2][8][4];
    #pragma unroll
    for (int mi = 0; mi < 2; mi++)
        #pragma unroll
        for (int ni = 0; ni < 8; ni++)
            #pragma unroll
            for (int r = 0; r < 4; r++) acc[mi][ni][r] = 0.f;

    int a_r  = tid >> 2;                // 0..63
    int a_c4 = (tid & 3) * 4;           // 0,4,8,12
    int b_r  = tid >> 4;                // 0..15
    int b_c8 = (tid & 15) * 8;          // 0..120

    const float* Abase = A + (size_t)(row0 + a_r) * K + a_c4;
    const float* Wbase = W + (size_t)b_r * N + col0 + b_c8;

    uint32_t a_dst0 = (uint32_t)__cvta_generic_to_shared(&As[0][a_r][a_c4]);
    uint32_t a_dst1 = (uint32_t)__cvta_generic_to_shared(&As[0][a_r + 64][a_c4]);
    uint32_t b_dst0 = (uint32_t)__cvta_generic_to_shared(&Bs[0][b_r][b_c8]);
    uint32_t b_dst1 = b_dst0 + 16;

    // prologue: stage 0
    cp_async16(a_dst0, Abase);
    cp_async16(a_dst1, Abase + (size_t)64 * K);
    cp_async16(b_dst0, Wbase);
    cp_async16(b_dst1, Wbase + 4);
    asm volatile("cp.async.commit_group;" ::: "memory");

    int cur = 0;
    for (int k0 = 0; k0 < K; k0 += BKK, cur ^= 1) {
        asm volatile("cp.async.wait_group 0;" ::: "memory");
        __syncthreads();

        int kn = k0 + BKK;
        if (kn < K) {
            uint32_t aoff = (cur ^ 1) ? A_STAGE : 0;
            uint32_t boff = (cur ^ 1) ? B_STAGE : 0;
            cp_async16(a_dst0 + aoff, Abase + kn);
            cp_async16(a_dst1 + aoff, Abase + (size_t)64 * K + kn);
            cp_async16(b_dst0 + boff, Wbase + (size_t)kn * N);
            cp_async16(b_dst1 + boff, Wbase + (size_t)kn * N + 4);
            asm volatile("cp.async.commit_group;" ::: "memory");
        }

        #pragma unroll
        for (int kk = 0; kk < 2; kk++) {
            int kb = kk * 8;
            uint32_t a[2][4];
            #pragma unroll
            for (int mi = 0; mi < 2; mi++) {
                int rb = warpM + mi*16 + (lane >> 2);
                int cb = kb + (lane & 3);
                a[mi][0] = __float_as_uint(As[cur][rb    ][cb    ]);
                a[mi][1] = __float_as_uint(As[cur][rb + 8][cb    ]);
                a[mi][2] = __float_as_uint(As[cur][rb    ][cb + 4]);
                a[mi][3] = __float_as_uint(As[cur][rb + 8][cb + 4]);
            }
            uint32_t b[8][2];
            #pragma unroll
            for (int ni = 0; ni < 8; ni++) {
                int nb_ = warpN + ni*8 + (lane >> 2);
                int kr  = kb + (lane & 3);
                b[ni][0] = __float_as_uint(Bs[cur][kr    ][nb_]);
                b[ni][1] = __float_as_uint(Bs[cur][kr + 4][nb_]);
            }
            #pragma unroll
            for (int mi = 0; mi < 2; mi++)
                #pragma unroll
                for (int ni = 0; ni < 8; ni++)
                    mma_tf32(acc[mi][ni], a[mi][0], a[mi][1], a[mi][2], a[mi][3],
                             b[ni][0], b[ni][1]);
        }
    }

    // epilogue
    #pragma unroll
    for (int mi = 0; mi < 2; mi++) {
        #pragma unroll
        for (int ni = 0; ni < 8; ni++) {
            int r0 = row0 + warpM + mi*16 + (lane >> 2);
            int c  = col0 + warpN + ni*8 + (lane & 3)*2;
            float2 lo = make_float2(acc[mi][ni][0], acc[mi][ni][1]);
            float2 hi = make_float2(acc[mi][ni][2], acc[mi][ni][3]);
            if (bias) {
                float2 bv = *(const float2*)(bias + c);
                lo.x += bv.x; lo.y += bv.y;
                hi.x += bv.x; hi.y += bv.y;
            }
            size_t o0 = (size_t)r0 * N + c;
            size_t o1 = (size_t)(r0 + 8) * N + c;
            if (res) {
                float2 r0v = *(const float2*)(res + o0);
                float2 r1v = *(const float2*)(res + o1);
                lo.x += r0v.x; lo.y += r0v.y;
                hi.x += r1v.x; hi.y += r1v.y;
            }
            if (do_relu) {
                lo.x = fmaxf(lo.x, 0.f); lo.y = fmaxf(lo.y, 0.f);
                hi.x = fmaxf(hi.x, 0.f); hi.y = fmaxf(hi.y, 0.f);
            }
            if (round_out) {
                lo.x = rnd_tf32(lo.x); lo.y = rnd_tf32(lo.y);
                hi.x = rnd_tf32(hi.x); hi.y = rnd_tf32(hi.y);
            }
            *(float2*)(C + o0) = lo;
            *(float2*)(C + o1) = hi;
        }
    }
}

// ---------------- flash-style causal attention ------------------------------
// block = (qtile of 128 rows, head, batch); 128 threads; thread owns 1 q row.
// Output tf32-rounded (feeds proj GEMM).
#define KTILE 64
#define KVPITCH 68

__global__ __launch_bounds__(128)
void attn_kernel(const float* __restrict__ q, const float* __restrict__ k,
                 const float* __restrict__ v, float* __restrict__ o)
{
    __shared__ float Ks[KTILE][KVPITCH];
    __shared__ float Vs[KTILE][KVPITCH];

    int qt  = blockIdx.x;
    int hh  = blockIdx.y;
    int b   = blockIdx.z;
    int tid = threadIdx.x;
    int r    = qt * 128 + tid;
    int grow = b * TT + r;
    int col0 = hh * DD;

    float4 q4[16], o4[16];
    const float4* qp = (const float4*)(q + (size_t)grow * EE + col0);
    #pragma unroll
    for (int i = 0; i < 16; i++) {
        float4 t = qp[i];
        t.x *= 0.125f; t.y *= 0.125f; t.z *= 0.125f; t.w *= 0.125f;
        q4[i] = t;
        o4[i] = make_float4(0.f, 0.f, 0.f, 0.f);
    }
    float m = -INFINITY, l = 0.f;

    int ntiles = (qt * 128 + 128) / KTILE;
    int tr = tid >> 1;
    int tc = (tid & 1) * 32;

    for (int kt = 0; kt < ntiles; kt++) {
        int krow = b * TT + kt * KTILE + tr;
        const float4* ksrc = (const float4*)(k + (size_t)krow * EE + col0 + tc);
        const float4* vsrc = (const float4*)(v + (size_t)krow * EE + col0 + tc);
        float4* kdst = (float4*)&Ks[tr][tc];
        float4* vdst = (float4*)&Vs[tr][tc];
        #pragma unroll
        for (int i = 0; i < 8; i++) { kdst[i] = ksrc[i]; vdst[i] = vsrc[i]; }
        __syncthreads();

        int jmax = r - kt * KTILE + 1;
        if (jmax > KTILE) jmax = KTILE;
        for (int j = 0; j < jmax; j++) {
            const float4* kr4 = (const float4*)&Ks[j][0];
            float s0 = 0.f, s1 = 0.f, s2 = 0.f, s3 = 0.f;
            #pragma unroll
            for (int i = 0; i < 16; i++) {
                float4 kv = kr4[i];
                s0 += q4[i].x * kv.x; s1 += q4[i].y * kv.y;
                s2 += q4[i].z * kv.z; s3 += q4[i].w * kv.w;
            }
            float s = (s0 + s1) + (s2 + s3);
            float mn = fmaxf(m, s);
            float corr = expf(m - mn);
            float p = expf(s - mn);
            l = l * corr + p;
            m = mn;
            const float4* vr4 = (const float4*)&Vs[j][0];
            #pragma unroll
            for (int i = 0; i < 16; i++) {
                float4 vv = vr4[i];
                o4[i].x = o4[i].x * corr + p * vv.x;
                o4[i].y = o4[i].y * corr + p * vv.y;
                o4[i].z = o4[i].z * corr + p * vv.z;
                o4[i].w = o4[i].w * corr + p * vv.w;
            }
        }
        __syncthreads();
    }

    float inv = 1.f / l;
    float4* op = (float4*)(o + (size_t)grow * EE + col0);
    #pragma unroll
    for (int i = 0; i < 16; i++) {
        float4 t = o4[i];
        t.x = rnd_tf32(t.x * inv); t.y = rnd_tf32(t.y * inv);
        t.z = rnd_tf32(t.z * inv); t.w = rnd_tf32(t.w * inv);
        op[i] = t;
    }
}

// ---------------- host: full forward pass ----------------
extern "C" void kernel_launch(void* const* d_in, const int* in_sizes, int n_in,
                              void* d_out, int out_size)
{
    (void)in_sizes; (void)n_in;
    const int*   idx    = (const int*)  d_in[0];
    const float* tok    = (const float*)d_in[1];
    const float* pos    = (const float*)d_in[2];
    const float* Wq     = (const float*)d_in[3];
    const float* Wk     = (const float*)d_in[4];
    const float* Wv     = (const float*)d_in[5];
    const float* Wproj  = (const float*)d_in[6];
    const float* bproj  = (const float*)d_in[7];
    const float* ln1g   = (const float*)d_in[8];
    const float* ln1b   = (const float*)d_in[9];
    const float* ln2g   = (const float*)d_in[10];
    const float* ln2b   = (const float*)d_in[11];
    const float* W1     = (const float*)d_in[12];
    const float* b1     = (const float*)d_in[13];
    const float* W2     = (const float*)d_in[14];
    const float* b2     = (const float*)d_in[15];
    const float* lnfg   = (const float*)d_in[16];
    const float* lnfb   = (const float*)d_in[17];
    const float* Wlm    = (const float*)d_in[18];
    const float* blm    = (const float*)d_in[19];
    float* out = (float*)d_out;
    (void)out_size;

    float *px, *ph, *pq, *pk, *pv, *po, *pf;
    float *cwq, *cwk, *cwv, *cwp, *cw1, *cw2, *cwlm;
    cudaGetSymbolAddress((void**)&px, g_x);
    cudaGetSymbolAddress((void**)&ph, g_h);
    cudaGetSymbolAddress((void**)&pq, g_q);
    cudaGetSymbolAddress((void**)&pk, g_k);
    cudaGetSymbolAddress((void**)&pv, g_v);
    cudaGetSymbolAddress((void**)&po, g_o);
    cudaGetSymbolAddress((void**)&pf, g_f);
    cudaGetSymbolAddress((void**)&cwq, g_cwq);
    cudaGetSymbolAddress((void**)&cwk, g_cwk);
    cudaGetSymbolAddress((void**)&cwv, g_cwv);
    cudaGetSymbolAddress((void**)&cwp, g_cwp);
    cudaGetSymbolAddress((void**)&cw1, g_cw1);
    cudaGetSymbolAddress((void**)&cw2, g_cw2);
    cudaGetSymbolAddress((void**)&cwlm, g_cwlm);

    // pre-round all weights to tf32
    cvt_kernel<<<(S4/4 + 255)/256, 256>>>(Wq,    cwq,  S4/4);
    cvt_kernel<<<(S4/4 + 255)/256, 256>>>(Wk,    cwk,  S4/4);
    cvt_kernel<<<(S4/4 + 255)/256, 256>>>(Wv,    cwv,  S4/4);
    cvt_kernel<<<(S4/4 + 255)/256, 256>>>(Wproj, cwp,  S4/4);
    cvt_kernel<<<(SF/4 + 255)/256, 256>>>(W1,    cw1,  SF/4);
    cvt_kernel<<<(SF/4 + 255)/256, 256>>>(W2,    cw2,  SF/4);
    cvt_kernel<<<(SLM/4 + 255)/256, 256>>>(Wlm,  cwlm, SLM/4);

    dim3 blk256(256);
    dim3 gridLN(MM);

    embed_kernel<<<MM, 256>>>(idx, tok, pos);

    dim3 gQKV(EE/BN, MM/BM, 3);   // 8 x 16 x 3
    dim3 gE(EE/BN,  MM/BM, 1);    // 8 x 16
    dim3 gF(FFN/BN, MM/BM, 1);    // 32 x 16
    dim3 gV(VV/BN,  MM/BM, 1);    // 250 x 16
    dim3 gAttn(TT/128, HH, BB);

    for (int l = 0; l < LL; l++) {
        size_t offE2 = (size_t)l * EE * EE;
        size_t offEF = (size_t)l * EE * FFN;
        ln_kernel<<<gridLN, blk256>>>(px, ln1g + l*EE, ln1b + l*EE, ph);
        tgemm_kernel<<<gQKV, blk256>>>(ph, cwq + offE2, cwk + offE2, cwv + offE2,
                                       nullptr, nullptr, pq, pk, pv,
                                       MM, EE, EE, 0, 0);
        attn_kernel<<<gAttn, 128>>>(pq, pk, pv, po);
        tgemm_kernel<<<gE, blk256>>>(po, cwp + offE2, cwp + offE2, cwp + offE2,
                                     bproj + l*EE, px, px, px, px,
                                     MM, EE, EE, 0, 0);
        ln_kernel<<<gridLN, blk256>>>(px, ln2g + l*EE, ln2b + l*EE, ph);
        tgemm_kernel<<<gF, blk256>>>(ph, cw1 + offEF, cw1 + offEF, cw1 + offEF,
                                     b1 + (size_t)l*FFN, nullptr, pf, pf, pf,
                                     MM, FFN, EE, 1, 1);
        tgemm_kernel<<<gE, blk256>>>(pf, cw2 + offEF, cw2 + offEF, cw2 + offEF,
                                     b2 + l*EE, px, px, px, px,
                                     MM, EE, FFN, 0, 0);
    }

    ln_kernel<<<gridLN, blk256>>>(px, lnfg, lnfb, ph);
    tgemm_kernel<<<gV, blk256>>>(ph, cwlm, cwlm, cwlm,
                                 blm, nullptr, out, out, out,
                                 MM, VV, EE, 0, 0);
}

// round 13
// speedup vs baseline: 3.2478x; 1.0368x over previous
#include <cuda_runtime.h>
#include <cuda_bf16.h>
#include <stdint.h>
#include <math.h>

// ---------------- problem constants ----------------
#define BB   2
#define TT   1024
#define EE   1024
#define HH   16
#define DD   64
#define FFN  4096
#define VV   32000
#define LL   6
#define MM   (BB*TT)          // 2048 rows

#define S4   (LL*EE*EE)
#define SF   (LL*EE*FFN)
#define SLM  (EE*VV)

// ---------------- scratch ----------
__device__ float g_x[MM*EE];
__device__ float g_h[MM*EE];
__device__ float g_q[MM*EE];
__device__ float g_k[MM*EE];
__device__ float g_v[MM*EE];
__device__ float g_o[MM*EE];
__device__ float g_f[MM*FFN];
__device__ float g_cwq[S4];
__device__ float g_cwk[S4];
__device__ float g_cwv[S4];
__device__ float g_cwp[S4];
__device__ float g_cw1[SF];
__device__ float g_cw2[SF];
__device__ float g_cwlm[SLM];

__device__ __forceinline__ uint32_t f2tf32(float f) {
    uint32_t r;
    asm("cvt.rna.tf32.f32 %0, %1;" : "=r"(r) : "f"(f));
    return r;
}
__device__ __forceinline__ float rnd_tf32(float f) {
    return __uint_as_float(f2tf32(f));
}

// ---------------- weight pre-rounding ----------------
__global__ void cvt_kernel(const float* __restrict__ src, float* __restrict__ dst, int n4)
{
    int i = blockIdx.x * blockDim.x + threadIdx.x;
    if (i < n4) {
        float4 v = ((const float4*)src)[i];
        float4 o;
        o.x = rnd_tf32(v.x); o.y = rnd_tf32(v.y);
        o.z = rnd_tf32(v.z); o.w = rnd_tf32(v.w);
        ((float4*)dst)[i] = o;
    }
}

// ---------------- embedding ----------------
__global__ void embed_kernel(const int* __restrict__ idx,
                             const float* __restrict__ tok,
                             const float* __restrict__ pos)
{
    int row = blockIdx.x;
    int t   = row & (TT-1);
    int tokid = idx[row];
    const float4* t4 = (const float4*)(tok + (size_t)tokid * EE);
    const float4* p4 = (const float4*)(pos + (size_t)t * EE);
    float4* x4 = (float4*)(g_x + (size_t)row * EE);
    int j = threadIdx.x;
    float4 a = t4[j], b = p4[j];
    a.x += b.x; a.y += b.y; a.z += b.z; a.w += b.w;
    x4[j] = a;
}

// ---------------- layernorm (tf32-rounded output) --------
__global__ void ln_kernel(const float* __restrict__ x,
                          const float* __restrict__ g,
                          const float* __restrict__ b,
                          float* __restrict__ y)
{
    __shared__ float red[256];
    __shared__ float s_mu, s_inv;
    int row = blockIdx.x;
    int tid = threadIdx.x;
    const float4* xr = (const float4*)(x + (size_t)row * EE);
    float4 xv = xr[tid];

    float s = xv.x + xv.y + xv.z + xv.w;
    red[tid] = s; __syncthreads();
    for (int o = 128; o > 0; o >>= 1) { if (tid < o) red[tid] += red[tid+o]; __syncthreads(); }
    if (tid == 0) s_mu = red[0] * (1.0f/EE);
    __syncthreads();
    float mu = s_mu;

    float d0 = xv.x-mu, d1 = xv.y-mu, d2 = xv.z-mu, d3 = xv.w-mu;
    s = d0*d0 + d1*d1 + d2*d2 + d3*d3;
    __syncthreads();
    red[tid] = s; __syncthreads();
    for (int o = 128; o > 0; o >>= 1) { if (tid < o) red[tid] += red[tid+o]; __syncthreads(); }
    if (tid == 0) s_inv = rsqrtf(red[0] * (1.0f/EE) + 1e-5f);
    __syncthreads();
    float inv = s_inv;

    float4 gv = ((const float4*)g)[tid];
    float4 bv = ((const float4*)b)[tid];
    float4 out;
    out.x = rnd_tf32(d0*inv*gv.x + bv.x);
    out.y = rnd_tf32(d1*inv*gv.y + bv.y);
    out.z = rnd_tf32(d2*inv*gv.z + bv.z);
    out.w = rnd_tf32(d3*inv*gv.w + bv.w);
    ((float4*)(y + (size_t)row * EE))[tid] = out;
}

// ---------------- TF32 tensor-core GEMM helpers ----------------------------
#define BM  128
#define BKK 16
#define APAD 20

__device__ __forceinline__ void mma_tf32(float c[4], uint32_t a0, uint32_t a1,
                                         uint32_t a2, uint32_t a3,
                                         uint32_t b0, uint32_t b1) {
    asm volatile(
        "mma.sync.aligned.m16n8k8.row.col.f32.tf32.tf32.f32 "
        "{%0,%1,%2,%3}, {%4,%5,%6,%7}, {%8,%9}, {%0,%1,%2,%3};"
        : "+f"(c[0]), "+f"(c[1]), "+f"(c[2]), "+f"(c[3])
        : "r"(a0), "r"(a1), "r"(a2), "r"(a3), "r"(b0), "r"(b1));
}

__device__ __forceinline__ void cp_async16(uint32_t dst, const float* src) {
    asm volatile("cp.async.cg.shared.global [%0], [%1], 16;" :: "r"(dst), "l"(src));
}

// ===================== tgemm64: BN=64, 3-stage ==============================
// 256 thr = 8 warps (4 M x 2 N), warp tile 32x32.
#define BN64     64
#define BP64     72
#define A_STG    (BM*APAD*4)          // 10240 bytes
#define B_STG64  (BKK*BP64*4)         // 4608 bytes

__global__ __launch_bounds__(256, 2)
void tgemm64_kernel(const float* __restrict__ A,
                    const float* __restrict__ W0, const float* __restrict__ W1p,
                    const float* __restrict__ W2p,
                    const float* __restrict__ bias, const float* __restrict__ res,
                    float* __restrict__ C0, float* __restrict__ C1p, float* __restrict__ C2p,
                    int M, int N, int K, int do_relu, int round_out)
{
    __shared__ float As[3][BM][APAD];
    __shared__ float Bs[3][BKK][BP64];

    const float* W = (blockIdx.z == 0) ? W0 : ((blockIdx.z == 1) ? W1p : W2p);
    float*       C = (blockIdx.z == 0) ? C0 : ((blockIdx.z == 1) ? C1p : C2p);

    int tid  = threadIdx.x;
    int lane = tid & 31;
    int warp = tid >> 5;
    int warpM = (warp & 3) * 32;
    int warpN = (warp >> 2) * 32;

    int row0 = blockIdx.y * BM;
    int col0 = blockIdx.x * BN64;

    float acc[2][4][4];
    #pragma unroll
    for (int mi = 0; mi < 2; mi++)
        #pragma unroll
        for (int ni = 0; ni < 4; ni++)
            #pragma unroll
            for (int r = 0; r < 4; r++) acc[mi][ni][r] = 0.f;

    int a_r  = tid >> 2;
    int a_c4 = (tid & 3) * 4;
    int b_r  = tid >> 4;
    int b_c  = (tid & 15) * 4;

    const float* Abase = A + (size_t)(row0 + a_r) * K + a_c4;
    const float* Wbase = W + (size_t)b_r * N + col0 + b_c;

    uint32_t a_dst0 = (uint32_t)__cvta_generic_to_shared(&As[0][a_r][a_c4]);
    uint32_t a_dst1 = (uint32_t)__cvta_generic_to_shared(&As[0][a_r + 64][a_c4]);
    uint32_t b_dst  = (uint32_t)__cvta_generic_to_shared(&Bs[0][b_r][b_c]);

    // prologue: stages 0,1
    cp_async16(a_dst0, Abase);
    cp_async16(a_dst1, Abase + (size_t)64 * K);
    cp_async16(b_dst,  Wbase);
    asm volatile("cp.async.commit_group;" ::: "memory");
    cp_async16(a_dst0 + A_STG, Abase + BKK);
    cp_async16(a_dst1 + A_STG, Abase + (size_t)64 * K + BKK);
    cp_async16(b_dst + B_STG64, Wbase + (size_t)BKK * N);
    asm volatile("cp.async.commit_group;" ::: "memory");

    int cur = 0;
    for (int k0 = 0; k0 < K; k0 += BKK) {
        asm volatile("cp.async.wait_group 1;" ::: "memory");
        __syncthreads();

        int kpre = k0 + 2 * BKK;
        int nxt = cur + 2; if (nxt >= 3) nxt -= 3;
        if (kpre < K) {
            cp_async16(a_dst0 + nxt*A_STG, Abase + kpre);
            cp_async16(a_dst1 + nxt*A_STG, Abase + (size_t)64 * K + kpre);
            cp_async16(b_dst + nxt*B_STG64, Wbase + (size_t)kpre * N);
        }
        asm volatile("cp.async.commit_group;" ::: "memory");

        #pragma unroll
        for (int kk = 0; kk < 2; kk++) {
            int kb = kk * 8;
            uint32_t a[2][4];
            #pragma unroll
            for (int mi = 0; mi < 2; mi++) {
                int rb = warpM + mi*16 + (lane >> 2);
                int cb = kb + (lane & 3);
                a[mi][0] = __float_as_uint(As[cur][rb    ][cb    ]);
                a[mi][1] = __float_as_uint(As[cur][rb + 8][cb    ]);
                a[mi][2] = __float_as_uint(As[cur][rb    ][cb + 4]);
                a[mi][3] = __float_as_uint(As[cur][rb + 8][cb + 4]);
            }
            uint32_t b[4][2];
            #pragma unroll
            for (int ni = 0; ni < 4; ni++) {
                int nb_ = warpN + ni*8 + (lane >> 2);
                int kr  = kb + (lane & 3);
                b[ni][0] = __float_as_uint(Bs[cur][kr    ][nb_]);
                b[ni][1] = __float_as_uint(Bs[cur][kr + 4][nb_]);
            }
            #pragma unroll
            for (int mi = 0; mi < 2; mi++)
                #pragma unroll
                for (int ni = 0; ni < 4; ni++)
                    mma_tf32(acc[mi][ni], a[mi][0], a[mi][1], a[mi][2], a[mi][3],
                             b[ni][0], b[ni][1]);
        }
        cur++; if (cur >= 3) cur = 0;
    }

    #pragma unroll
    for (int mi = 0; mi < 2; mi++) {
        #pragma unroll
        for (int ni = 0; ni < 4; ni++) {
            int r0 = row0 + warpM + mi*16 + (lane >> 2);
            int c  = col0 + warpN + ni*8 + (lane & 3)*2;
            float2 lo = make_float2(acc[mi][ni][0], acc[mi][ni][1]);
            float2 hi = make_float2(acc[mi][ni][2], acc[mi][ni][3]);
            if (bias) {
                float2 bv = *(const float2*)(bias + c);
                lo.x += bv.x; lo.y += bv.y;
                hi.x += bv.x; hi.y += bv.y;
            }
            size_t o0 = (size_t)r0 * N + c;
            size_t o1 = (size_t)(r0 + 8) * N + c;
            if (res) {
                float2 r0v = *(const float2*)(res + o0);
                float2 r1v = *(const float2*)(res + o1);
                lo.x += r0v.x; lo.y += r0v.y;
                hi.x += r1v.x; hi.y += r1v.y;
            }
            if (do_relu) {
                lo.x = fmaxf(lo.x, 0.f); lo.y = fmaxf(lo.y, 0.f);
                hi.x = fmaxf(hi.x, 0.f); hi.y = fmaxf(hi.y, 0.f);
            }
            if (round_out) {
                lo.x = rnd_tf32(lo.x); lo.y = rnd_tf32(lo.y);
                hi.x = rnd_tf32(hi.x); hi.y = rnd_tf32(hi.y);
            }
            *(float2*)(C + o0) = lo;
            *(float2*)(C + o1) = hi;
        }
    }
}

// ===================== tgemm128: BN=128, 2-stage ============================
// 256 thr = 8 warps (4 M x 2 N), warp tile 32x64.
#define BN128    128
#define BP128    136
#define B_STG128 (BKK*BP128*4)        // 8704 bytes

__global__ __launch_bounds__(256, 2)
void tgemm128_kernel(const float* __restrict__ A,
                     const float* __restrict__ W0,
                     const float* __restrict__ bias, const float* __restrict__ res,
                     float* __restrict__ C0,
                     int M, int N, int K, int do_relu, int round_out)
{
    __shared__ float As[2][BM][APAD];
    __shared__ float Bs[2][BKK][BP128];

    const float* W = W0;
    float*       C = C0;

    int tid  = threadIdx.x;
    int lane = tid & 31;
    int warp = tid >> 5;
    int warpM = (warp & 3) * 32;
    int warpN = (warp >> 2) * 64;

    int row0 = blockIdx.y * BM;
    int col0 = blockIdx.x * BN128;

    float acc[2][8][4];
    #pragma unroll
    for (int mi = 0; mi < 2; mi++)
        #pragma unroll
        for (int ni = 0; ni < 8; ni++)
            #pragma unroll
            for (int r = 0; r < 4; r++) acc[mi][ni][r] = 0.f;

    int a_r  = tid >> 2;
    int a_c4 = (tid & 3) * 4;
    int b_r  = tid >> 4;
    int b_c  = (tid & 15) * 8;

    const float* Abase = A + (size_t)(row0 + a_r) * K + a_c4;
    const float* Wbase = W + (size_t)b_r * N + col0 + b_c;

    uint32_t a_dst0 = (uint32_t)__cvta_generic_to_shared(&As[0][a_r][a_c4]);
    uint32_t a_dst1 = (uint32_t)__cvta_generic_to_shared(&As[0][a_r + 64][a_c4]);
    uint32_t b_dst  = (uint32_t)__cvta_generic_to_shared(&Bs[0][b_r][b_c]);

    // prologue: stage 0
    cp_async16(a_dst0, Abase);
    cp_async16(a_dst1, Abase + (size_t)64 * K);
    cp_async16(b_dst,      Wbase);
    cp_async16(b_dst + 16, Wbase + 4);
    asm volatile("cp.async.commit_group;" ::: "memory");

    int cur = 0;
    for (int k0 = 0; k0 < K; k0 += BKK) {
        asm volatile("cp.async.wait_group 0;" ::: "memory");
        __syncthreads();

        int kpre = k0 + BKK;
        int nxt = cur ^ 1;
        if (kpre < K) {
            cp_async16(a_dst0 + nxt*A_STG, Abase + kpre);
            cp_async16(a_dst1 + nxt*A_STG, Abase + (size_t)64 * K + kpre);
            cp_async16(b_dst + nxt*B_STG128,      Wbase + (size_t)kpre * N);
            cp_async16(b_dst + nxt*B_STG128 + 16, Wbase + (size_t)kpre * N + 4);
        }
        asm volatile("cp.async.commit_group;" ::: "memory");

        #pragma unroll
        for (int kk = 0; kk < 2; kk++) {
            int kb = kk * 8;
            uint32_t a[2][4];
            #pragma unroll
            for (int mi = 0; mi < 2; mi++) {
                int rb = warpM + mi*16 + (lane >> 2);
                int cb = kb + (lane & 3);
                a[mi][0] = __float_as_uint(As[cur][rb    ][cb    ]);
                a[mi][1] = __float_as_uint(As[cur][rb + 8][cb    ]);
                a[mi][2] = __float_as_uint(As[cur][rb    ][cb + 4]);
                a[mi][3] = __float_as_uint(As[cur][rb + 8][cb + 4]);
            }
            uint32_t b[8][2];
            #pragma unroll
            for (int ni = 0; ni < 8; ni++) {
                int nb_ = warpN + ni*8 + (lane >> 2);
                int kr  = kb + (lane & 3);
                b[ni][0] = __float_as_uint(Bs[cur][kr    ][nb_]);
                b[ni][1] = __float_as_uint(Bs[cur][kr + 4][nb_]);
            }
            #pragma unroll
            for (int mi = 0; mi < 2; mi++)
                #pragma unroll
                for (int ni = 0; ni < 8; ni++)
                    mma_tf32(acc[mi][ni], a[mi][0], a[mi][1], a[mi][2], a[mi][3],
                             b[ni][0], b[ni][1]);
        }
        cur ^= 1;
    }

    #pragma unroll
    for (int mi = 0; mi < 2; mi++) {
        #pragma unroll
        for (int ni = 0; ni < 8; ni++) {
            int r0 = row0 + warpM + mi*16 + (lane >> 2);
            int c  = col0 + warpN + ni*8 + (lane & 3)*2;
            float2 lo = make_float2(acc[mi][ni][0], acc[mi][ni][1]);
            float2 hi = make_float2(acc[mi][ni][2], acc[mi][ni][3]);
            if (bias) {
                float2 bv = *(const float2*)(bias + c);
                lo.x += bv.x; lo.y += bv.y;
                hi.x += bv.x; hi.y += bv.y;
            }
            size_t o0 = (size_t)r0 * N + c;
            size_t o1 = (size_t)(r0 + 8) * N + c;
            if (res) {
                float2 r0v = *(const float2*)(res + o0);
                float2 r1v = *(const float2*)(res + o1);
                lo.x += r0v.x; lo.y += r0v.y;
                hi.x += r1v.x; hi.y += r1v.y;
            }
            if (do_relu) {
                lo.x = fmaxf(lo.x, 0.f); lo.y = fmaxf(lo.y, 0.f);
                hi.x = fmaxf(hi.x, 0.f); hi.y = fmaxf(hi.y, 0.f);
            }
            if (round_out) {
                lo.x = rnd_tf32(lo.x); lo.y = rnd_tf32(lo.y);
                hi.x = rnd_tf32(hi.x); hi.y = rnd_tf32(hi.y);
            }
            *(float2*)(C + o0) = lo;
            *(float2*)(C + o1) = hi;
        }
    }
}

// ---------------- flash-style causal attention ------------------------------
#define KTILE 64
#define KVPITCH 68

__global__ __launch_bounds__(128)
void attn_kernel(const float* __restrict__ q, const float* __restrict__ k,
                 const float* __restrict__ v, float* __restrict__ o)
{
    __shared__ float Ks[KTILE][KVPITCH];
    __shared__ float Vs[KTILE][KVPITCH];

    int qt  = blockIdx.x;
    int hh  = blockIdx.y;
    int b   = blockIdx.z;
    int tid = threadIdx.x;
    int r    = qt * 128 + tid;
    int grow = b * TT + r;
    int col0 = hh * DD;

    float4 q4[16], o4[16];
    const float4* qp = (const float4*)(q + (size_t)grow * EE + col0);
    #pragma unroll
    for (int i = 0; i < 16; i++) {
        float4 t = qp[i];
        t.x *= 0.125f; t.y *= 0.125f; t.z *= 0.125f; t.w *= 0.125f;
        q4[i] = t;
        o4[i] = make_float4(0.f, 0.f, 0.f, 0.f);
    }
    float m = -INFINITY, l = 0.f;

    int ntiles = (qt * 128 + 128) / KTILE;
    int tr = tid >> 1;
    int tc = (tid & 1) * 32;

    for (int kt = 0; kt < ntiles; kt++) {
        int krow = b * TT + kt * KTILE + tr;
        const float4* ksrc = (const float4*)(k + (size_t)krow * EE + col0 + tc);
        const float4* vsrc = (const float4*)(v + (size_t)krow * EE + col0 + tc);
        float4* kdst = (float4*)&Ks[tr][tc];
        float4* vdst = (float4*)&Vs[tr][tc];
        #pragma unroll
        for (int i = 0; i < 8; i++) { kdst[i] = ksrc[i]; vdst[i] = vsrc[i]; }
        __syncthreads();

        int jmax = r - kt * KTILE + 1;
        if (jmax > KTILE) jmax = KTILE;
        for (int j = 0; j < jmax; j++) {
            const float4* kr4 = (const float4*)&Ks[j][0];
            float s0 = 0.f, s1 = 0.f, s2 = 0.f, s3 = 0.f;
            #pragma unroll
            for (int i = 0; i < 16; i++) {
                float4 kv = kr4[i];
                s0 += q4[i].x * kv.x; s1 += q4[i].y * kv.y;
                s2 += q4[i].z * kv.z; s3 += q4[i].w * kv.w;
            }
            float s = (s0 + s1) + (s2 + s3);
            float mn = fmaxf(m, s);
            float corr = expf(m - mn);
            float p = expf(s - mn);
            l = l * corr + p;
            m = mn;
            const float4* vr4 = (const float4*)&Vs[j][0];
            #pragma unroll
            for (int i = 0; i < 16; i++) {
                float4 vv = vr4[i];
                o4[i].x = o4[i].x * corr + p * vv.x;
                o4[i].y = o4[i].y * corr + p * vv.y;
                o4[i].z = o4[i].z * corr + p * vv.z;
                o4[i].w = o4[i].w * corr + p * vv.w;
            }
        }
        __syncthreads();
    }

    float inv = 1.f / l;
    float4* op = (float4*)(o + (size_t)grow * EE + col0);
    #pragma unroll
    for (int i = 0; i < 16; i++) {
        float4 t = o4[i];
        t.x = rnd_tf32(t.x * inv); t.y = rnd_tf32(t.y * inv);
        t.z = rnd_tf32(t.z * inv); t.w = rnd_tf32(t.w * inv);
        op[i] = t;
    }
}

// ---------------- host: full forward pass ----------------
extern "C" void kernel_launch(void* const* d_in, const int* in_sizes, int n_in,
                              void* d_out, int out_size)
{
    (void)in_sizes; (void)n_in;
    const int*   idx    = (const int*)  d_in[0];
    const float* tok    = (const float*)d_in[1];
    const float* pos    = (const float*)d_in[2];
    const float* Wq     = (const float*)d_in[3];
    const float* Wk     = (const float*)d_in[4];
    const float* Wv     = (const float*)d_in[5];
    const float* Wproj  = (const float*)d_in[6];
    const float* bproj  = (const float*)d_in[7];
    const float* ln1g   = (const float*)d_in[8];
    const float* ln1b   = (const float*)d_in[9];
    const float* ln2g   = (const float*)d_in[10];
    const float* ln2b   = (const float*)d_in[11];
    const float* W1     = (const float*)d_in[12];
    const float* b1     = (const float*)d_in[13];
    const float* W2     = (const float*)d_in[14];
    const float* b2     = (const float*)d_in[15];
    const float* lnfg   = (const float*)d_in[16];
    const float* lnfb   = (const float*)d_in[17];
    const float* Wlm    = (const float*)d_in[18];
    const float* blm    = (const float*)d_in[19];
    float* out = (float*)d_out;
    (void)out_size;

    float *px, *ph, *pq, *pk, *pv, *po, *pf;
    float *cwq, *cwk, *cwv, *cwp, *cw1, *cw2, *cwlm;
    cudaGetSymbolAddress((void**)&px, g_x);
    cudaGetSymbolAddress((void**)&ph, g_h);
    cudaGetSymbolAddress((void**)&pq, g_q);
    cudaGetSymbolAddress((void**)&pk, g_k);
    cudaGetSymbolAddress((void**)&pv, g_v);
    cudaGetSymbolAddress((void**)&po, g_o);
    cudaGetSymbolAddress((void**)&pf, g_f);
    cudaGetSymbolAddress((void**)&cwq, g_cwq);
    cudaGetSymbolAddress((void**)&cwk, g_cwk);
    cudaGetSymbolAddress((void**)&cwv, g_cwv);
    cudaGetSymbolAddress((void**)&cwp, g_cwp);
    cudaGetSymbolAddress((void**)&cw1, g_cw1);
    cudaGetSymbolAddress((void**)&cw2, g_cw2);
    cudaGetSymbolAddress((void**)&cwlm, g_cwlm);

    cvt_kernel<<<(S4/4 + 255)/256, 256>>>(Wq,    cwq,  S4/4);
    cvt_kernel<<<(S4/4 + 255)/256, 256>>>(Wk,    cwk,  S4/4);
    cvt_kernel<<<(S4/4 + 255)/256, 256>>>(Wv,    cwv,  S4/4);
    cvt_kernel<<<(S4/4 + 255)/256, 256>>>(Wproj, cwp,  S4/4);
    cvt_kernel<<<(SF/4 + 255)/256, 256>>>(W1,    cw1,  SF/4);
    cvt_kernel<<<(SF/4 + 255)/256, 256>>>(W2,    cw2,  SF/4);
    cvt_kernel<<<(SLM/4 + 255)/256, 256>>>(Wlm,  cwlm, SLM/4);

    dim3 blk256(256);
    dim3 gridLN(MM);

    embed_kernel<<<MM, 256>>>(idx, tok, pos);

    dim3 gQKV(EE/64,  MM/BM, 3);   // 16 x 16 x 3
    dim3 gE64(EE/64,  MM/BM, 1);   // 16 x 16
    dim3 gF(FFN/128,  MM/BM, 1);   // 32 x 16
    dim3 gV(VV/128,   MM/BM, 1);   // 250 x 16
    dim3 gAttn(TT/128, HH, BB);

    for (int l = 0; l < LL; l++) {
        size_t offE2 = (size_t)l * EE * EE;
        size_t offEF = (size_t)l * EE * FFN;
        ln_kernel<<<gridLN, blk256>>>(px, ln1g + l*EE, ln1b + l*EE, ph);
        tgemm64_kernel<<<gQKV, blk256>>>(ph, cwq + offE2, cwk + offE2, cwv + offE2,
                                         nullptr, nullptr, pq, pk, pv,
                                         MM, EE, EE, 0, 0);
        attn_kernel<<<gAttn, 128>>>(pq, pk, pv, po);
        tgemm64_kernel<<<gE64, blk256>>>(po, cwp + offE2, cwp + offE2, cwp + offE2,
                                         bproj + l*EE, px, px, px, px,
                                         MM, EE, EE, 0, 0);
        ln_kernel<<<gridLN, blk256>>>(px, ln2g + l*EE, ln2b + l*EE, ph);
        tgemm128_kernel<<<gF, blk256>>>(ph, cw1 + offEF,
                                        b1 + (size_t)l*FFN, nullptr, pf,
                                        MM, FFN, EE, 1, 1);
        tgemm64_kernel<<<gE64, blk256>>>(pf, cw2 + offEF, cw2 + offEF, cw2 + offEF,
                                        b2 + l*EE, px, px, px, px,
                                        MM, EE, FFN, 0, 0);
    }

    ln_kernel<<<gridLN, blk256>>>(px, lnfg, lnfb, ph);
    tgemm128_kernel<<<gV, blk256>>>(ph, cwlm,
                                    blm, nullptr, out,
                                    MM, VV, EE, 0, 0);
}